// round 6
// baseline (speedup 1.0000x reference)
#include <cuda_runtime.h>
#include <cuda_bf16.h>
#include <cstddef>

// Depthwise cross-correlation, channel-PAIRED with packed fp32x2 FMA:
//   out[ch, oy, ox] = sum_{ky,kx} x[ch, oy+ky, ox+kx] * z[ch, ky, kx]
//   32768 channels, x: 31x31, z: 7x7, out: 25x25 (VALID, no flip)
//
// R5: two adjacent channels are processed per thread as a float2 lane pair,
// using PTX fma.rn.f32x2 (Blackwell packed fp32). All operands (x, taps,
// accumulators) are naturally 64-bit pairs -> zero repacking overhead.

#define NCHAN   (128 * 256)
#define NPAIR   (NCHAN / 2)     // 16384
#define HX      31
#define HZ      7
#define HO      25
#define XSZ     (HX * HX)       // 961
#define ZSZ     (HZ * HZ)       // 49
#define OSZ     (HO * HO)       // 625
#define PPB     5               // channel-pairs per block
#define TPC     25              // threads per pair (one per output column)
#define THREADS 128
// float2 channel pitch: 969 ≡ 9 (mod 16) -> LDS.64 is bank-conflict-free for
// the (lp, tx) lane layout in every half-warp phase of all 4 warps (verified).
#define XP2     969

__device__ __forceinline__ void ffma2(float2& d, const float2& a, const float2& b) {
    asm("fma.rn.f32x2 %0, %1, %2, %0;"
        : "+l"(reinterpret_cast<unsigned long long&>(d))
        : "l"(reinterpret_cast<const unsigned long long&>(a)),
          "l"(reinterpret_cast<const unsigned long long&>(b)));
}

__global__ __launch_bounds__(THREADS, 3)
void dwxcorr2_kernel(const float* __restrict__ z,
                     const float* __restrict__ x,
                     float* __restrict__ out) {
    __shared__ float2 sx[PPB * XP2];   // 38760 B
    __shared__ float2 sk[PPB * ZSZ];   //  1960 B

    const int tid      = threadIdx.x;
    const int pairBase = blockIdx.x * PPB;

    // ---- Stage: interleave each channel pair (ch0, ch1) as float2 ----
    #pragma unroll
    for (int lp = 0; lp < PPB; ++lp) {
        const int p = pairBase + lp;
        if (p < NPAIR) {
            const float* g0 = x + (size_t)(2 * p) * XSZ;
            const float* g1 = g0 + XSZ;
            for (int i = tid; i < XSZ; i += THREADS)
                sx[lp * XP2 + i] = make_float2(g0[i], g1[i]);
            if (tid < ZSZ) {
                const float* z0 = z + (size_t)(2 * p) * ZSZ;
                sk[lp * ZSZ + tid] = make_float2(z0[tid], z0[tid + ZSZ]);
            }
        }
    }
    __syncthreads();

    const int lp = tid / TPC;            // local pair 0..4 (5 = idle lanes)
    const int tx = tid - lp * TPC;       // output column 0..24
    const int p  = pairBase + lp;
    if (lp >= PPB || p >= NPAIR) return;

    // 49 packed taps in registers (98 regs) — broadcast LDS.64, no conflicts.
    float2 kk[ZSZ];
    #pragma unroll
    for (int j = 0; j < ZSZ; ++j) kk[j] = sk[lp * ZSZ + j];

    // Ring of 7 packed accumulators: at x-row r, output rows [r-6, r] live.
    float2 acc[HZ];
    #pragma unroll
    for (int i = 0; i < HZ; ++i) acc[i] = make_float2(0.0f, 0.0f);

    const float2* xb  = &sx[lp * XP2 + tx];
    float*        go0 = out + (size_t)(2 * p) * OSZ + tx;
    float*        go1 = go0 + OSZ;

    #pragma unroll
    for (int r = 0; r < HX; ++r) {
        float2 xr[HZ];
        #pragma unroll
        for (int c = 0; c < HZ; ++c)
            xr[c] = xb[r * HX + c];

        #pragma unroll
        for (int ky = 0; ky < HZ; ++ky) {
            const int oy = r - ky;
            if (oy >= 0 && oy < HO) {
                const int slot = oy % HZ;          // const after unroll
                #pragma unroll
                for (int kx = 0; kx < HZ; ++kx)
                    ffma2(acc[slot], xr[kx], kk[ky * HZ + kx]);
            }
        }

        // Output row r-6 complete: store both channels, recycle the slot.
        if (r >= HZ - 1) {
            const int oy   = r - (HZ - 1);
            const int slot = oy % HZ;
            go0[oy * HO] = acc[slot].x;
            go1[oy * HO] = acc[slot].y;
            acc[slot] = make_float2(0.0f, 0.0f);
        }
    }
}

extern "C" void kernel_launch(void* const* d_in, const int* in_sizes, int n_in,
                              void* d_out, int out_size) {
    // metadata order: d_in[0] = z_f [128,256,7,7], d_in[1] = x_f [128,256,31,31]
    const float* z = (const float*)d_in[0];
    const float* x = (const float*)d_in[1];
    float* out = (float*)d_out;

    const int grid = (NPAIR + PPB - 1) / PPB;   // 3277
    dwxcorr2_kernel<<<grid, THREADS>>>(z, x, out);
}

// round 7
// speedup vs baseline: 1.0646x; 1.0646x over previous
#include <cuda_runtime.h>
#include <cuda_bf16.h>
#include <cstddef>
#include <cstdint>

// Depthwise cross-correlation, persistent CTAs + cp.async double-buffered
// pipeline + channel-paired fp32x2 FMA.
//   out[ch, oy, ox] = sum_{ky,kx} x[ch, oy+ky, ox+kx] * z[ch, ky, kx]
//   32768 channels, x: 31x31, z: 7x7, out: 25x25 (VALID, no flip)
//
// R6 diagnosis: R4/R5 were memory-LATENCY bound (dur*BW == bytes moved, HBM
// at 22% of peak): staging and compute alternated with nothing in flight.
// R6: grid = 152 persistent CTAs; while computing group i from SMEM buffer A,
// group i+1 streams into buffer B via cp.async (no LDG->STS reg dependency).

#define NCHAN   32768
#define NPAIR   16384
#define HX      31
#define HZ      7
#define HO      25
#define XSZ     961
#define ZSZ     49
#define OSZ     625
#define PPB     10              // channel-pairs per group (20 channels)
#define TPC     25              // threads per pair (one per output column)
#define THREADS 256
#define GRID    152             // persistent: one CTA per SM (GB300)
#define NGROUPS 1639            // 1638 full groups + 1 tail group of 4 pairs

#define GX_FLOATS (PPB * 2 * XSZ)   // 19220 floats per full group (76880 B, 16B-aligned)
#define GZ_FLOATS (PPB * 2 * ZSZ)   //   980 floats
#define GX_V4     (GX_FLOATS / 4)   //  4805
#define GZ_V4     (GZ_FLOATS / 4)   //   245
#define TAILX_V4  1922              // 4 pairs: 7688 floats / 4
#define TAILZ_V4  98                // 4 pairs:  392 floats / 4

__device__ __forceinline__ void ffma2(float2& d, const float2& a, const float2& b) {
    asm("fma.rn.f32x2 %0, %1, %2, %0;"
        : "+l"(reinterpret_cast<unsigned long long&>(d))
        : "l"(reinterpret_cast<const unsigned long long&>(a)),
          "l"(reinterpret_cast<const unsigned long long&>(b)));
}

__device__ __forceinline__ void cpasync16(uint32_t saddr, const void* gaddr) {
    asm volatile("cp.async.cg.shared.global [%0], [%1], 16;"
                 :: "r"(saddr), "l"(gaddr) : "memory");
}
#define CP_COMMIT() asm volatile("cp.async.commit_group;" ::: "memory")
#define CP_WAIT1()  asm volatile("cp.async.wait_group 1;" ::: "memory")
#define CP_WAIT0()  asm volatile("cp.async.wait_group 0;" ::: "memory")

__device__ __forceinline__ void prefetch_group(
    int g, float* xs, float* zs,
    const float* __restrict__ x, const float* __restrict__ z, int tid)
{
    const bool tail = (g == NGROUPS - 1);
    const int nxv = tail ? TAILX_V4 : GX_V4;
    const int nzv = tail ? TAILZ_V4 : GZ_V4;
    const float4* gx = reinterpret_cast<const float4*>(x) + (size_t)g * GX_V4;
    const float4* gz = reinterpret_cast<const float4*>(z) + (size_t)g * GZ_V4;
    const uint32_t sx = (uint32_t)__cvta_generic_to_shared(xs);
    const uint32_t sz = (uint32_t)__cvta_generic_to_shared(zs);
    for (int j = tid; j < nxv; j += THREADS)
        cpasync16(sx + (uint32_t)j * 16u, gx + j);
    for (int j = tid; j < nzv; j += THREADS)
        cpasync16(sz + (uint32_t)j * 16u, gz + j);
}

__device__ __forceinline__ void compute_group(
    int g, const float* __restrict__ xs, const float* __restrict__ zs,
    float* __restrict__ out, int lp, int tx)
{
    const int p = g * PPB + lp;
    if (lp >= PPB || p >= NPAIR) return;    // no syncs inside: safe divergence

    const float* x0 = xs + (2 * lp) * XSZ;  // even channel of the pair
    const float* x1 = x0 + XSZ;             // odd channel
    const float* z0 = zs + (2 * lp) * ZSZ;
    const float* z1 = z0 + ZSZ;

    // 49 packed taps in registers.
    float2 kk[ZSZ];
    #pragma unroll
    for (int j = 0; j < ZSZ; ++j) kk[j] = make_float2(z0[j], z1[j]);

    // Ring of 7 packed accumulators: at x-row r, output rows [r-6, r] live.
    float2 acc[HZ];
    #pragma unroll
    for (int i = 0; i < HZ; ++i) acc[i] = make_float2(0.0f, 0.0f);

    float* go0 = out + (size_t)(2 * p) * OSZ + tx;
    float* go1 = go0 + OSZ;

    #pragma unroll
    for (int r = 0; r < HX; ++r) {
        float2 xr[HZ];
        #pragma unroll
        for (int c = 0; c < HZ; ++c)
            xr[c] = make_float2(x0[r * HX + tx + c], x1[r * HX + tx + c]);

        #pragma unroll
        for (int ky = 0; ky < HZ; ++ky) {
            const int oy = r - ky;
            if (oy >= 0 && oy < HO) {
                const int slot = oy % HZ;          // const after unroll
                #pragma unroll
                for (int kx = 0; kx < HZ; ++kx)
                    ffma2(acc[slot], xr[kx], kk[ky * HZ + kx]);
            }
        }

        if (r >= HZ - 1) {                         // row r-6 complete
            const int oy   = r - (HZ - 1);
            const int slot = oy % HZ;
            go0[oy * HO] = acc[slot].x;
            go1[oy * HO] = acc[slot].y;
            acc[slot] = make_float2(0.0f, 0.0f);
        }
    }
}

__global__ __launch_bounds__(THREADS, 1)
void dwxcorr_pipe(const float* __restrict__ z,
                  const float* __restrict__ x,
                  float* __restrict__ out) {
    extern __shared__ float smem[];
    float* xb0 = smem;
    float* xb1 = smem + GX_FLOATS;
    float* zb0 = smem + 2 * GX_FLOATS;
    float* zb1 = zb0 + GZ_FLOATS;

    const int tid = threadIdx.x;
    const int lp  = tid / TPC;       // local pair 0..9 (>=10: copy-only lanes)
    const int tx  = tid - lp * TPC;  // output column 0..24

    int g = blockIdx.x;
    if (g < NGROUPS)
        prefetch_group(g, xb0, zb0, x, z, tid);
    CP_COMMIT();

    int i = 0;
    for (; g < NGROUPS; g += GRID, ++i) {
        float* xc = (i & 1) ? xb1 : xb0;
        float* zc = (i & 1) ? zb1 : zb0;
        float* xn = (i & 1) ? xb0 : xb1;
        float* zn = (i & 1) ? zb0 : zb1;

        const int gn = g + GRID;
        if (gn < NGROUPS) {
            prefetch_group(gn, xn, zn, x, z, tid);   // background fill
            CP_COMMIT();
            CP_WAIT1();                               // current group landed
        } else {
            CP_WAIT0();
        }
        __syncthreads();                              // data visible to all

        compute_group(g, xc, zc, out, lp, tx);

        __syncthreads();                              // done reading xc/zc
    }
}

extern "C" void kernel_launch(void* const* d_in, const int* in_sizes, int n_in,
                              void* d_out, int out_size) {
    // metadata order: d_in[0] = z_f [128,256,7,7], d_in[1] = x_f [128,256,31,31]
    const float* z = (const float*)d_in[0];
    const float* x = (const float*)d_in[1];
    float* out = (float*)d_out;

    const size_t smem = (size_t)(2 * GX_FLOATS + 2 * GZ_FLOATS) * sizeof(float); // 161600 B
    cudaFuncSetAttribute(dwxcorr_pipe,
                         cudaFuncAttributeMaxDynamicSharedMemorySize, (int)smem);
    dwxcorr_pipe<<<GRID, THREADS, smem>>>(z, x, out);
}